// round 15
// baseline (speedup 1.0000x reference)
#include <cuda_runtime.h>
#include <cuda_bf16.h>

// Problem constants
#define T_   4
#define B_   2
#define C_   384
#define L_   1024
#define H_   8
#define D_   48
#define C2_  768
#define BH_  16            // B_*H_
#define BCL  (B_*C_*L_)    // 786432
#define LL   (L_*L_)       // 1048576

typedef unsigned long long u64;
typedef unsigned short u16;
typedef unsigned char u8;

// Scratch (device globals; zero-initialized at module load)
__device__ __nv_bfloat16 g_xsb [T_*BCL];           // x spikes, bf16 {0,1}
__device__ __nv_bfloat16 g_Ws  [3*C2_*C_];         // W_w 3-split
__device__ __nv_bfloat16 g_Pws [3*C_*C_];          // proj_w 3-split (2 used)
__device__ __nv_bfloat16 g_y1s [8*H_*3*48*L_];     // y1 3-split [t2b][h][s][48][l]
__device__ __nv_bfloat16 g_y2s [8*H_*3*64*L_];     // y2 3-split [t2b][h][s][64][l] (48 used)
__device__ u8            g_spkU[T_*BH_*LL];        // attn spikes u8 [z][m][l] (64MB)
__device__ float         g_o1  [T_*BCL];           // out1 fp32 [c][m]
__device__ __nv_bfloat16 g_o1b [T_*BCL];           // out1 spikes bf16

// ---- mma.sync / ldmatrix / cp.async helpers (compute_103-safe) ----
__device__ __forceinline__ unsigned smem_u32(const void* p) {
    unsigned r;
    asm("{ .reg .u64 t; cvta.to.shared.u64 t, %1; cvt.u32.u64 %0, t; }" : "=r"(r) : "l"(p));
    return r;
}
__device__ __forceinline__ void ldsm_x4(unsigned* r, unsigned addr) {
    asm volatile("ldmatrix.sync.aligned.m8n8.x4.shared.b16 {%0,%1,%2,%3}, [%4];"
                 : "=r"(r[0]), "=r"(r[1]), "=r"(r[2]), "=r"(r[3]) : "r"(addr));
}
__device__ __forceinline__ void ldsm_x4t(unsigned* r, unsigned addr) {
    asm volatile("ldmatrix.sync.aligned.m8n8.x4.trans.shared.b16 {%0,%1,%2,%3}, [%4];"
                 : "=r"(r[0]), "=r"(r[1]), "=r"(r[2]), "=r"(r[3]) : "r"(addr));
}
__device__ __forceinline__ void mma16816(float* d, const unsigned* a, const unsigned* b) {
    asm volatile(
        "mma.sync.aligned.m16n8k16.row.col.f32.bf16.bf16.f32 "
        "{%0,%1,%2,%3},{%4,%5,%6,%7},{%8,%9},{%0,%1,%2,%3};"
        : "+f"(d[0]), "+f"(d[1]), "+f"(d[2]), "+f"(d[3])
        : "r"(a[0]), "r"(a[1]), "r"(a[2]), "r"(a[3]), "r"(b[0]), "r"(b[1]));
}
__device__ __forceinline__ void cp16(unsigned s, const void* g) {
    asm volatile("cp.async.cg.shared.global [%0], [%1], 16;" :: "r"(s), "l"(g));
}
__device__ __forceinline__ void cp_commit() {
    asm volatile("cp.async.commit_group;" ::: "memory");
}
__device__ __forceinline__ void cp_wait0() {
    asm volatile("cp.async.wait_group 0;" ::: "memory");
}
__device__ __forceinline__ void cp_wait1() {
    asm volatile("cp.async.wait_group 1;" ::: "memory");
}
__device__ __forceinline__ u16 bf_bits(__nv_bfloat16 h) { return *(u16*)&h; }

// u8 spike pair (u16: b0 | b1<<8) -> packed bf16x2 {0,1}, exact, 2 ALU ops
__device__ __forceinline__ unsigned spk_frag(const u8* p) {
    unsigned x = *(const u16*)p;
    return __byte_perm(0x00003F80u, 0u, 0x2222u - x * 0x12u);
}

// ---------------------------------------------------------------------------
// K1: fused prep — membrane scan of x -> bf16 spikes, plus 3-split of weights.
// ---------------------------------------------------------------------------
__global__ __launch_bounds__(256) void k_prep(const float* __restrict__ x,
                                              const float* __restrict__ W,
                                              const float* __restrict__ P) {
    int bid = blockIdx.x;
    if (bid < BCL / 256) {
        int i = bid * 256 + threadIdx.x;
        float mem = 0.f, sp = 0.f;
#pragma unroll
        for (int t = 0; t < T_; ++t) {
            mem = mem * 0.25f * (1.f - sp) + x[(size_t)t * BCL + i];
            sp  = (mem > 0.5f) ? 1.f : 0.f;
            ((u16*)g_xsb)[(size_t)t * BCL + i] = (mem > 0.5f) ? 0x3F80 : 0;
        }
    } else {
        int i = (bid - BCL / 256) * 256 + threadIdx.x;   // < 442368
        float v; __nv_bfloat16* base; int plane;
        if (i < C2_ * C_) { v = W[i]; base = g_Ws;  plane = C2_ * C_; }
        else { i -= C2_ * C_; v = P[i]; base = g_Pws; plane = C_ * C_; }
        __nv_bfloat16 b0 = __float2bfloat16(v);  v -= __bfloat162float(b0);
        __nv_bfloat16 b1 = __float2bfloat16(v);  v -= __bfloat162float(b1);
        __nv_bfloat16 b2 = __float2bfloat16(v);
        base[i] = b0; base[i + plane] = b1; base[i + 2 * plane] = b2;
    }
}

// ---------------------------------------------------------------------------
// K2/K6: HMMA GEMM  D[m][n] = sum_{s,k} Wsplit_s[m][k] * Xspk[k][n], bn epilogue
//   3-stage single-sync cp.async pipeline over 12 k-chunks of 32.
// ---------------------------------------------------------------------------
#define WP_A 40
#define WP_B 72
template<int NSPLIT, int MODE>
__global__ __launch_bounds__(256, 2) void k_wgemm(
    const float* __restrict__ gamma, const float* __restrict__ beta,
    const float* __restrict__ mean,  const float* __restrict__ var,
    const float* __restrict__ resid, float* __restrict__ outp, int M)
{
    constexpr int AE  = NSPLIT * 128 * WP_A;     // A elems per stage
    constexpr int STG = AE + 32 * WP_B;          // stage elems
    extern __shared__ __nv_bfloat16 dyn[];
    const __nv_bfloat16* Wsrc = MODE ? g_Pws : g_Ws;
    const __nv_bfloat16* X = (MODE ? g_o1b : g_xsb) + (size_t)blockIdx.z * (C_ * L_);
    const int t2b = blockIdx.z;
    const int m0 = blockIdx.y * 128, n0 = blockIdx.x * 64;
    const int tid = threadIdx.x, lane = tid & 31, wid = tid >> 5;
    const int wm = wid & 3, wl = wid >> 2;
    const unsigned sDyn = smem_u32(dyn);

    float acc[2][4][4] = {};
    const int a_r = wm * 32 + (lane & 15);
    const int a_c = (lane >> 4) * 8;
    const int b_r = (lane & 7) + ((lane >> 3) & 1) * 8;
    const int b_c = wl * 32 + ((lane >> 4) & 1) * 8;

    auto load_stage = [&](int kc, int buf) {
        const int k0 = kc * 32;
        unsigned base = sDyn + buf * (STG * 2);
#pragma unroll
        for (int q = 0; q < 2 * NSPLIT; ++q) {               // A: NSPLIT*512 cp16
            int id = tid + q * 256;
            int s = id >> 9, r = (id >> 2) & 127, c = id & 3;
            cp16(base + 2u * ((s * 128 + r) * WP_A + c * 8),
                 Wsrc + (size_t)s * M * C_ + (size_t)(m0 + r) * C_ + k0 + c * 8);
        }
        {                                                    // B: 256 cp16
            int r = tid >> 3, c = tid & 7;
            cp16(base + 2u * (AE + r * WP_B + c * 8),
                 X + (size_t)(k0 + r) * L_ + n0 + c * 8);
        }
        cp_commit();
    };

    load_stage(0, 0);
    load_stage(1, 1);
    for (int kc = 0; kc < 12; ++kc) {
        if (kc < 11) cp_wait1(); else cp_wait0();
        __syncthreads();                          // visibility + WAR guard
        if (kc < 10) load_stage(kc + 2, (kc + 2) % 3);
        const unsigned sA = sDyn + (kc % 3) * (STG * 2);
        const unsigned sB = sA + AE * 2;

        unsigned bfr[2][4][2];
#pragma unroll
        for (int kk = 0; kk < 2; ++kk)
#pragma unroll
            for (int pair = 0; pair < 2; ++pair) {
                unsigned bb[4];
                ldsm_x4t(bb, sB + 2u * ((kk * 16 + b_r) * WP_B + b_c + pair * 16));
                bfr[kk][pair * 2][0] = bb[0]; bfr[kk][pair * 2][1] = bb[1];
                bfr[kk][pair * 2 + 1][0] = bb[2]; bfr[kk][pair * 2 + 1][1] = bb[3];
            }
#pragma unroll
        for (int s = 0; s < NSPLIT; ++s)
#pragma unroll
            for (int kk = 0; kk < 2; ++kk) {
                unsigned a[2][4];
#pragma unroll
                for (int mi = 0; mi < 2; ++mi)
                    ldsm_x4(a[mi], sA + 2u * ((s * 128 + a_r + mi * 16) * WP_A + kk * 16 + a_c));
#pragma unroll
                for (int mi = 0; mi < 2; ++mi)
#pragma unroll
                    for (int ni = 0; ni < 4; ++ni)
                        mma16816(acc[mi][ni], a[mi], bfr[kk][ni]);
            }
    }

    // Epilogue: bn-apply into vv
    float vv[2][2][4][2];
#pragma unroll
    for (int mi = 0; mi < 2; ++mi)
#pragma unroll
        for (int u = 0; u < 2; ++u) {
            int m = m0 + wm * 32 + mi * 16 + (lane >> 2) + u * 8;
            float inv = gamma[m] / sqrtf(var[m] + 1e-5f);
            float off = beta[m] - mean[m] * inv;
#pragma unroll
            for (int ni = 0; ni < 4; ++ni) {
                vv[mi][u][ni][0] = acc[mi][ni][u * 2 + 0] * inv + off;
                vv[mi][u][ni][1] = acc[mi][ni][u * 2 + 1] * inv + off;
            }
        }

    if (MODE) {
        const int nb = n0 + wl * 32 + (lane & 3) * 2;
#pragma unroll
        for (int mi = 0; mi < 2; ++mi)
#pragma unroll
            for (int u = 0; u < 2; ++u) {
                int m = m0 + wm * 32 + mi * 16 + (lane >> 2) + u * 8;
#pragma unroll
                for (int ni = 0; ni < 4; ++ni) {
                    int n = nb + ni * 8;
                    const float2 rx = *(const float2*)(resid + (size_t)t2b * (C_ * L_) +
                                                       (size_t)m * L_ + n);
                    *(float2*)(outp + (size_t)t2b * (C_ * L_) + (size_t)m * L_ + n) =
                        make_float2(vv[mi][u][ni][0] + rx.x, vv[mi][u][ni][1] + rx.y);
                }
            }
    } else {
        // 3 split passes staged through smem (stage buffers free now)
        u16* stg = (u16*)dyn;
        __syncthreads();
#pragma unroll
        for (int s = 0; s < 3; ++s) {
#pragma unroll
            for (int mi = 0; mi < 2; ++mi)
#pragma unroll
                for (int u = 0; u < 2; ++u) {
                    int ml = wm * 32 + mi * 16 + (lane >> 2) + u * 8;
#pragma unroll
                    for (int ni = 0; ni < 4; ++ni) {
                        int nl = wl * 32 + ni * 8 + (lane & 3) * 2;
                        __nv_bfloat16 h0 = __float2bfloat16(vv[mi][u][ni][0]);
                        vv[mi][u][ni][0] -= __bfloat162float(h0);
                        __nv_bfloat16 h1 = __float2bfloat16(vv[mi][u][ni][1]);
                        vv[mi][u][ni][1] -= __bfloat162float(h1);
                        *(ushort2*)&stg[ml * 72 + nl] =
                            make_ushort2(bf_bits(h0), bf_bits(h1));
                    }
                }
            __syncthreads();
#pragma unroll
            for (int q = 0; q < 4; ++q) {
                int idx = tid + q * 256, r = idx >> 3, c = idx & 7;
                uint4 w = *(uint4*)&stg[r * 72 + c * 8];
                int m = m0 + r, hh = m / 96, rr = m % 96;
                u16* dst;
                if (rr < 48)
                    dst = (u16*)g_y1s + ((size_t)(t2b * 8 + hh) * 3 + s) * 49152 +
                          (size_t)rr * 1024 + n0 + c * 8;
                else
                    dst = (u16*)g_y2s + ((size_t)(t2b * 8 + hh) * 3 + s) * 65536 +
                          (size_t)(rr - 48) * 1024 + n0 + c * 8;
                *(uint4*)dst = w;
            }
            __syncthreads();
        }
    }
}

// ---------------------------------------------------------------------------
// K3: HMMA attn  attnT[m][l] = sum_{s,d} xr[d][m] * y1s[s][d][l], fused t-scan
//   512 threads, 16 warps (8m x 2l), CTA 256m x 64l — halves y1s L2 re-reads.
//   Warp-level math identical to previous version (order-preserving).
//   smem: A[2][48*264] bf16 | B[2][144*72] bf16 | stg[2][256*80] u8
// ---------------------------------------------------------------------------
#define AP_A 264
#define AP_B 72
#define AT_AE (48 * AP_A)                   // 12672 elems
#define AT_STG (AT_AE + 144 * AP_B)         // 23040 elems per stage
__global__ __launch_bounds__(512, 1) void k_attn_mma() {
    extern __shared__ __nv_bfloat16 dyn[];
    const int bh = blockIdx.z, b = bh >> 3, h = bh & 7;
    const int m0 = blockIdx.y * 256, l0 = blockIdx.x * 64;
    const int tid = threadIdx.x, lane = tid & 31, wid = tid >> 5;
    const int wm = wid & 7, wl = wid >> 3;
    const unsigned sDyn = smem_u32(dyn);

    float mem[2][4][4];
#pragma unroll
    for (int i = 0; i < 2; ++i)
#pragma unroll
        for (int j = 0; j < 4; ++j)
#pragma unroll
            for (int q = 0; q < 4; ++q) mem[i][j][q] = 0.f;

    const int at_r = (lane & 7) + ((lane >> 4) & 1) * 8;
    const int at_c = wm * 32 + ((lane >> 3) & 1) * 8;
    const int bt_r = (lane & 7) + ((lane >> 3) & 1) * 8;
    const int bt_c = wl * 32 + ((lane >> 4) & 1) * 8;

    auto load_stage = [&](int t, int buf) {
        const int t2b = t * 2 + b;
        const __nv_bfloat16* xr = g_xsb + ((size_t)t2b * C_ + h * D_) * L_ + m0;
        const __nv_bfloat16* y1 = g_y1s + (size_t)(t2b * 8 + h) * 3 * 49152 + l0;
        unsigned base = sDyn + buf * (AT_STG * 2);
#pragma unroll
        for (int q = 0; q < 3; ++q) {                       // A: 1536 cp16 (48x256)
            int id = tid + q * 512;
            int r = id >> 5, c = id & 31;
            cp16(base + 2u * (r * AP_A + c * 8), xr + (size_t)r * L_ + c * 8);
        }
#pragma unroll
        for (int q = 0; q < 3; ++q) {                       // B: 1152 cp16 (144x64)
            int id = tid + q * 512;
            if (id < 1152) {
                int sr = id >> 3, c = id & 7;
                cp16(base + 2u * (AT_AE + sr * AP_B + c * 8), y1 + (size_t)sr * 1024 + c * 8);
            }
        }
        cp_commit();
    };

    u8* stg0 = (u8*)(dyn + 2 * AT_STG);      // two 256x80 u8 staging tiles
    u8* stgs[2] = {stg0, stg0 + 256 * 80};

    auto flush = [&](int t) {
        const u8* src = stgs[t & 1];
        u8* og = g_spkU + (size_t)(t * BH_ + bh) * LL;
#pragma unroll
        for (int q = 0; q < 2; ++q) {
            int idx = tid + q * 512, r = idx >> 2, c = idx & 3;
            uint4 w = *(const uint4*)&src[r * 80 + c * 16];
            *(uint4*)(og + (size_t)(m0 + r) * L_ + l0 + c * 16) = w;
        }
    };

    load_stage(0, 0);
#pragma unroll
    for (int t = 0; t < T_; ++t) {
        cp_wait0();
        __syncthreads();                       // visibility + WAR + stg ordering
        if (t < 3) load_stage(t + 1, (t + 1) & 1);
        if (t > 0) flush(t - 1);               // early: fills LDSM-dependency bubbles
        const unsigned sA = sDyn + (t & 1) * (AT_STG * 2);
        const unsigned sB = sA + AT_AE * 2;

        unsigned a[3][2][4];
#pragma unroll
        for (int kk = 0; kk < 3; ++kk)
#pragma unroll
            for (int mi = 0; mi < 2; ++mi)
                ldsm_x4t(a[kk][mi], sA + 2u * ((kk * 16 + at_r) * AP_A + at_c + mi * 16));

        float acc[2][4][4] = {};
#pragma unroll
        for (int s = 0; s < 3; ++s)
#pragma unroll
            for (int kk = 0; kk < 3; ++kk) {
                unsigned bfr[4][2];
#pragma unroll
                for (int pair = 0; pair < 2; ++pair) {
                    unsigned bb[4];
                    ldsm_x4t(bb, sB + 2u * ((s * 48 + kk * 16 + bt_r) * AP_B + bt_c + pair * 16));
                    bfr[pair * 2][0] = bb[0]; bfr[pair * 2][1] = bb[1];
                    bfr[pair * 2 + 1][0] = bb[2]; bfr[pair * 2 + 1][1] = bb[3];
                }
#pragma unroll
                for (int mi = 0; mi < 2; ++mi)
#pragma unroll
                    for (int ni = 0; ni < 4; ++ni)
                        mma16816(acc[mi][ni], a[kk][mi], bfr[ni]);
            }

        // membrane update + u8 spike staging
        u8* stg = stgs[t & 1];
#pragma unroll
        for (int mi = 0; mi < 2; ++mi)
#pragma unroll
            for (int u = 0; u < 2; ++u) {
                int ml = wm * 32 + mi * 16 + (lane >> 2) + u * 8;
#pragma unroll
                for (int ni = 0; ni < 4; ++ni) {
                    float* mp = &mem[mi][ni][u * 2];
                    mp[0] = mp[0] * 0.25f * ((mp[0] > 0.5f) ? 0.f : 1.f) + acc[mi][ni][u * 2];
                    mp[1] = mp[1] * 0.25f * ((mp[1] > 0.5f) ? 0.f : 1.f) + acc[mi][ni][u * 2 + 1];
                    int nl = wl * 32 + ni * 8 + (lane & 3) * 2;
                    *(uchar2*)&stg[ml * 80 + nl] =
                        make_uchar2(mp[0] > 0.5f ? 1 : 0, mp[1] > 0.5f ? 1 : 0);
                }
            }
    }
    __syncthreads();
    flush(3);
}

// ---------------------------------------------------------------------------
// K4: HMMA GEMM (transposed)  D[d][m] = sum_{s,l} y2s[s][d][l] * spk[m][l]
//   A = y2s (bf16, ldsm non-trans). B = spikes u8, expanded to 2-reg B-frags
//   via LDS.U16+PRMT (reused across all 3 splits). N-tile 256 -> grid 256 CTAs
//   (single resident wave). Output lands in g_o1's native [d][m] layout.
//   smem: A[2][144*72*2] | Bu8[2][256*80]
// ---------------------------------------------------------------------------
#define G2_AB   (144 * 72 * 2)              // 20736 B per A stage
#define G2_U8   (256 * 80)                  // 20480 B per B-u8 stage
#define OFF_U8  (2 * G2_AB)                 // 41472
#define G2_SMEM (OFF_U8 + 2 * G2_U8)        // 82432
__global__ __launch_bounds__(256, 2) void k_gemm2_mma() {
    extern __shared__ char dynG[];
    const int z  = blockIdx.y;
    const int m0 = blockIdx.x * 256;
    const int t = z >> 4, bh = z & 15, b = bh >> 3, h = bh & 7;
    const int t2b = t * 2 + b;

    const int tid = threadIdx.x, lane = tid & 31, wid = tid >> 5;
    const unsigned sDyn = smem_u32(dynG);

    const __nv_bfloat16* Agl = g_y2s + (size_t)(t2b * 8 + h) * 3 * 65536;
    const u8*            Bgl = g_spkU + (size_t)z * LL + (size_t)m0 * L_;

    float acc[3][4][4] = {};
    const int a_r = lane & 15;                 // + s*48 + mt*16
    const int a_c = (lane >> 4) * 8;           // + kk*16
    const int bn_row = lane >> 2;              // n within 8-row group
    const int bn_off = (lane & 3) * 2;         // k pair offset

    auto load_stage = [&](int it, int buf) {
        const int kt = it * 64;
        // A (y2s): 3 x 48 rows x 128B = 1152 cp16
#pragma unroll
        for (int q = 0; q < 5; ++q) {
            int id = tid + q * 256;
            if (id < 1152) {
                int s = id / 384, rr = (id % 384) >> 3, c = id & 7;
                cp16(sDyn + buf * G2_AB + 2u * ((s * 48 + rr) * 72 + c * 8),
                     Agl + (size_t)s * 65536 + (size_t)rr * 1024 + kt + c * 8);
            }
        }
        // B u8 (spikes): 256 rows x 64B = 1024 cp16
#pragma unroll
        for (int q = 0; q < 4; ++q) {
            int id = tid + q * 256, r = id >> 2, c = id & 3;
            cp16(sDyn + OFF_U8 + buf * G2_U8 + r * 80 + c * 16,
                 Bgl + (size_t)r * L_ + kt + c * 16);
        }
        cp_commit();
    };

    load_stage(0, 0);
    for (int it = 0; it < 16; ++it) {
        cp_wait0();
        __syncthreads();                          // visibility + WAR guard
        if (it < 15) load_stage(it + 1, (it + 1) & 1);

        const unsigned sA = sDyn + (it & 1) * G2_AB;
        const u8* Bu = (const u8*)(dynG + OFF_U8 + (it & 1) * G2_U8);

        // B fragments (spikes): expand once per chunk, reused across 3 splits
        unsigned bf[4][4][2];
#pragma unroll
        for (int nt = 0; nt < 4; ++nt)
#pragma unroll
            for (int kk = 0; kk < 4; ++kk) {
                const u8* p = Bu + (wid * 32 + nt * 8 + bn_row) * 80 + kk * 16 + bn_off;
                bf[nt][kk][0] = spk_frag(p);
                bf[nt][kk][1] = spk_frag(p + 8);
            }
#pragma unroll
        for (int s = 0; s < 3; ++s)
#pragma unroll
            for (int kk = 0; kk < 4; ++kk) {
                unsigned a[3][4];
#pragma unroll
                for (int mt = 0; mt < 3; ++mt)
                    ldsm_x4(a[mt], sA + 2u * ((s * 48 + mt * 16 + a_r) * 72 + kk * 16 + a_c));
#pragma unroll
                for (int mt = 0; mt < 3; ++mt)
#pragma unroll
                    for (int nt = 0; nt < 4; ++nt)
                        mma16816(acc[mt][nt], a[mt], bf[nt][kk]);
            }
    }

    // Epilogue: D[d][m] fragments -> g_o1 native layout (row-contiguous)
    float* O = g_o1 + (size_t)t2b * (C_ * L_) + (size_t)(h * D_) * L_;
#pragma unroll
    for (int mt = 0; mt < 3; ++mt) {
        int d = mt * 16 + (lane >> 2);
#pragma unroll
        for (int nt = 0; nt < 4; ++nt) {
            int m = m0 + wid * 32 + nt * 8 + (lane & 3) * 2;
            *(float2*)(O + (size_t)d * L_ + m)       = make_float2(acc[mt][nt][0], acc[mt][nt][1]);
            *(float2*)(O + (size_t)(d + 8) * L_ + m) = make_float2(acc[mt][nt][2], acc[mt][nt][3]);
        }
    }
}

// ---------------------------------------------------------------------------
// K5: membrane scan over out1 -> bf16 spikes
// ---------------------------------------------------------------------------
__global__ __launch_bounds__(256) void k_scan_o1() {
    int i = blockIdx.x * 256 + threadIdx.x;
    if (i >= BCL) return;
    float mem = 0.f, sp = 0.f;
#pragma unroll
    for (int t = 0; t < T_; ++t) {
        mem = mem * 0.25f * (1.f - sp) + g_o1[(size_t)t * BCL + i];
        sp  = (mem > 0.5f) ? 1.f : 0.f;
        ((u16*)g_o1b)[(size_t)t * BCL + i] = (mem > 0.5f) ? 0x3F80 : 0;
    }
}

// ---------------------------------------------------------------------------
extern "C" void kernel_launch(void* const* d_in, const int* in_sizes, int n_in,
                              void* d_out, int out_size) {
    (void)in_sizes; (void)n_in; (void)out_size;
    const float* x   = (const float*)d_in[0];
    const float* W_w = (const float*)d_in[1];
    const float* g1  = (const float*)d_in[2];
    const float* be1 = (const float*)d_in[3];
    const float* me1 = (const float*)d_in[4];
    const float* v1  = (const float*)d_in[5];
    const float* pw  = (const float*)d_in[6];
    const float* g2  = (const float*)d_in[7];
    const float* be2 = (const float*)d_in[8];
    const float* me2 = (const float*)d_in[9];
    const float* v2  = (const float*)d_in[10];
    float* out = (float*)d_out;

    const int smW0 = 3 * (3 * 128 * WP_A + 32 * WP_B) * 2;   // 105984
    const int smW1 = 3 * (2 * 128 * WP_A + 32 * WP_B) * 2;   // 75264
    const int smA  = 2 * AT_STG * 2 + 2 * 256 * 80;          // 133120
    const int smG  = G2_SMEM;                                // 82432
    cudaFuncSetAttribute(k_wgemm<3, 0>, cudaFuncAttributeMaxDynamicSharedMemorySize, smW0);
    cudaFuncSetAttribute(k_wgemm<2, 1>, cudaFuncAttributeMaxDynamicSharedMemorySize, smW1);
    cudaFuncSetAttribute(k_attn_mma,    cudaFuncAttributeMaxDynamicSharedMemorySize, smA);
    cudaFuncSetAttribute(k_gemm2_mma,   cudaFuncAttributeMaxDynamicSharedMemorySize, smG);

    k_prep<<<BCL / 256 + (C2_ * C_ + C_ * C_) / 256, 256>>>(x, W_w, pw);
    k_wgemm<3, 0><<<dim3(L_ / 64, C2_ / 128, T_ * B_), 256, smW0>>>(
        g1, be1, me1, v1, nullptr, nullptr, C2_);
    k_attn_mma<<<dim3(L_ / 64, L_ / 256, BH_), 512, smA>>>();
    k_gemm2_mma<<<dim3(L_ / 256, T_ * BH_), 256, smG>>>();
    k_scan_o1<<<BCL / 256, 256>>>();
    k_wgemm<2, 1><<<dim3(L_ / 64, C_ / 128, T_ * B_), 256, smW1>>>(
        g2, be2, me2, v2, x, out, C_);
}

// round 16
// speedup vs baseline: 1.0556x; 1.0556x over previous
#include <cuda_runtime.h>
#include <cuda_bf16.h>

// Problem constants
#define T_   4
#define B_   2
#define C_   384
#define L_   1024
#define H_   8
#define D_   48
#define C2_  768
#define BH_  16            // B_*H_
#define BCL  (B_*C_*L_)    // 786432
#define LL   (L_*L_)       // 1048576

typedef unsigned long long u64;
typedef unsigned short u16;
typedef unsigned char u8;

// Scratch (device globals; zero-initialized at module load)
__device__ __nv_bfloat16 g_xsb [T_*BCL];           // x spikes, bf16 {0,1}
__device__ __nv_bfloat16 g_Ws  [3*C2_*C_];         // W_w 3-split
__device__ __nv_bfloat16 g_Pws [3*C_*C_];          // proj_w 3-split (2 used)
__device__ __nv_bfloat16 g_y1s [8*H_*3*48*L_];     // y1 3-split [t2b][h][s][48][l]
__device__ __nv_bfloat16 g_y2s [8*H_*3*64*L_];     // y2 3-split [t2b][h][s][64][l] (48 used)
__device__ u8            g_spkU[T_*BH_*LL];        // attn spikes u8 [z][m][l] (64MB)
__device__ float         g_o1  [T_*BCL];           // out1 fp32 [c][m]
__device__ __nv_bfloat16 g_o1b [T_*BCL];           // out1 spikes bf16

// ---- mma.sync / ldmatrix / cp.async helpers (compute_103-safe) ----
__device__ __forceinline__ unsigned smem_u32(const void* p) {
    unsigned r;
    asm("{ .reg .u64 t; cvta.to.shared.u64 t, %1; cvt.u32.u64 %0, t; }" : "=r"(r) : "l"(p));
    return r;
}
__device__ __forceinline__ void ldsm_x4(unsigned* r, unsigned addr) {
    asm volatile("ldmatrix.sync.aligned.m8n8.x4.shared.b16 {%0,%1,%2,%3}, [%4];"
                 : "=r"(r[0]), "=r"(r[1]), "=r"(r[2]), "=r"(r[3]) : "r"(addr));
}
__device__ __forceinline__ void ldsm_x4t(unsigned* r, unsigned addr) {
    asm volatile("ldmatrix.sync.aligned.m8n8.x4.trans.shared.b16 {%0,%1,%2,%3}, [%4];"
                 : "=r"(r[0]), "=r"(r[1]), "=r"(r[2]), "=r"(r[3]) : "r"(addr));
}
__device__ __forceinline__ void mma16816(float* d, const unsigned* a, const unsigned* b) {
    asm volatile(
        "mma.sync.aligned.m16n8k16.row.col.f32.bf16.bf16.f32 "
        "{%0,%1,%2,%3},{%4,%5,%6,%7},{%8,%9},{%0,%1,%2,%3};"
        : "+f"(d[0]), "+f"(d[1]), "+f"(d[2]), "+f"(d[3])
        : "r"(a[0]), "r"(a[1]), "r"(a[2]), "r"(a[3]), "r"(b[0]), "r"(b[1]));
}
__device__ __forceinline__ void cp16(unsigned s, const void* g) {
    asm volatile("cp.async.cg.shared.global [%0], [%1], 16;" :: "r"(s), "l"(g));
}
__device__ __forceinline__ void cp_commit() {
    asm volatile("cp.async.commit_group;" ::: "memory");
}
__device__ __forceinline__ void cp_wait0() {
    asm volatile("cp.async.wait_group 0;" ::: "memory");
}
__device__ __forceinline__ void cp_wait1() {
    asm volatile("cp.async.wait_group 1;" ::: "memory");
}
__device__ __forceinline__ u16 bf_bits(__nv_bfloat16 h) { return *(u16*)&h; }

// u8 spike pair (u16: b0 | b1<<8) -> packed bf16x2 {0,1}, exact, 2 ALU ops
__device__ __forceinline__ unsigned spk_frag(const u8* p) {
    unsigned x = *(const u16*)p;
    return __byte_perm(0x00003F80u, 0u, 0x2222u - x * 0x12u);
}

// ---------------------------------------------------------------------------
// K1: fused prep — membrane scan of x -> bf16 spikes, plus 3-split of weights.
// ---------------------------------------------------------------------------
__global__ __launch_bounds__(256) void k_prep(const float* __restrict__ x,
                                              const float* __restrict__ W,
                                              const float* __restrict__ P) {
    int bid = blockIdx.x;
    if (bid < BCL / 256) {
        int i = bid * 256 + threadIdx.x;
        float mem = 0.f, sp = 0.f;
#pragma unroll
        for (int t = 0; t < T_; ++t) {
            mem = mem * 0.25f * (1.f - sp) + x[(size_t)t * BCL + i];
            sp  = (mem > 0.5f) ? 1.f : 0.f;
            ((u16*)g_xsb)[(size_t)t * BCL + i] = (mem > 0.5f) ? 0x3F80 : 0;
        }
    } else {
        int i = (bid - BCL / 256) * 256 + threadIdx.x;   // < 442368
        float v; __nv_bfloat16* base; int plane;
        if (i < C2_ * C_) { v = W[i]; base = g_Ws;  plane = C2_ * C_; }
        else { i -= C2_ * C_; v = P[i]; base = g_Pws; plane = C_ * C_; }
        __nv_bfloat16 b0 = __float2bfloat16(v);  v -= __bfloat162float(b0);
        __nv_bfloat16 b1 = __float2bfloat16(v);  v -= __bfloat162float(b1);
        __nv_bfloat16 b2 = __float2bfloat16(v);
        base[i] = b0; base[i + plane] = b1; base[i + 2 * plane] = b2;
    }
}

// ---------------------------------------------------------------------------
// K2/K6: HMMA GEMM  D[m][n] = sum_{s,k} Wsplit_s[m][k] * Xspk[k][n], bn epilogue
//   3-stage single-sync cp.async pipeline over 12 k-chunks of 32.
//   mode 0: 3-split epilogue staged in ONE pass (single barrier).
// ---------------------------------------------------------------------------
#define WP_A 40
#define WP_B 72
template<int NSPLIT, int MODE>
__global__ __launch_bounds__(256, 2) void k_wgemm(
    const float* __restrict__ gamma, const float* __restrict__ beta,
    const float* __restrict__ mean,  const float* __restrict__ var,
    const float* __restrict__ resid, float* __restrict__ outp, int M)
{
    constexpr int AE  = NSPLIT * 128 * WP_A;     // A elems per stage
    constexpr int STG = AE + 32 * WP_B;          // stage elems
    extern __shared__ __nv_bfloat16 dyn[];
    const __nv_bfloat16* Wsrc = MODE ? g_Pws : g_Ws;
    const __nv_bfloat16* X = (MODE ? g_o1b : g_xsb) + (size_t)blockIdx.z * (C_ * L_);
    const int t2b = blockIdx.z;
    const int m0 = blockIdx.y * 128, n0 = blockIdx.x * 64;
    const int tid = threadIdx.x, lane = tid & 31, wid = tid >> 5;
    const int wm = wid & 3, wl = wid >> 2;
    const unsigned sDyn = smem_u32(dyn);

    float acc[2][4][4] = {};
    const int a_r = wm * 32 + (lane & 15);
    const int a_c = (lane >> 4) * 8;
    const int b_r = (lane & 7) + ((lane >> 3) & 1) * 8;
    const int b_c = wl * 32 + ((lane >> 4) & 1) * 8;

    auto load_stage = [&](int kc, int buf) {
        const int k0 = kc * 32;
        unsigned base = sDyn + buf * (STG * 2);
#pragma unroll
        for (int q = 0; q < 2 * NSPLIT; ++q) {               // A: NSPLIT*512 cp16
            int id = tid + q * 256;
            int s = id >> 9, r = (id >> 2) & 127, c = id & 3;
            cp16(base + 2u * ((s * 128 + r) * WP_A + c * 8),
                 Wsrc + (size_t)s * M * C_ + (size_t)(m0 + r) * C_ + k0 + c * 8);
        }
        {                                                    // B: 256 cp16
            int r = tid >> 3, c = tid & 7;
            cp16(base + 2u * (AE + r * WP_B + c * 8),
                 X + (size_t)(k0 + r) * L_ + n0 + c * 8);
        }
        cp_commit();
    };

    load_stage(0, 0);
    load_stage(1, 1);
    for (int kc = 0; kc < 12; ++kc) {
        if (kc < 11) cp_wait1(); else cp_wait0();
        __syncthreads();                          // visibility + WAR guard
        if (kc < 10) load_stage(kc + 2, (kc + 2) % 3);
        const unsigned sA = sDyn + (kc % 3) * (STG * 2);
        const unsigned sB = sA + AE * 2;

        unsigned bfr[2][4][2];
#pragma unroll
        for (int kk = 0; kk < 2; ++kk)
#pragma unroll
            for (int pair = 0; pair < 2; ++pair) {
                unsigned bb[4];
                ldsm_x4t(bb, sB + 2u * ((kk * 16 + b_r) * WP_B + b_c + pair * 16));
                bfr[kk][pair * 2][0] = bb[0]; bfr[kk][pair * 2][1] = bb[1];
                bfr[kk][pair * 2 + 1][0] = bb[2]; bfr[kk][pair * 2 + 1][1] = bb[3];
            }
#pragma unroll
        for (int s = 0; s < NSPLIT; ++s)
#pragma unroll
            for (int kk = 0; kk < 2; ++kk) {
                unsigned a[2][4];
#pragma unroll
                for (int mi = 0; mi < 2; ++mi)
                    ldsm_x4(a[mi], sA + 2u * ((s * 128 + a_r + mi * 16) * WP_A + kk * 16 + a_c));
#pragma unroll
                for (int mi = 0; mi < 2; ++mi)
#pragma unroll
                    for (int ni = 0; ni < 4; ++ni)
                        mma16816(acc[mi][ni], a[mi], bfr[kk][ni]);
            }
    }

    // Epilogue: bn-apply into vv
    float vv[2][2][4][2];
#pragma unroll
    for (int mi = 0; mi < 2; ++mi)
#pragma unroll
        for (int u = 0; u < 2; ++u) {
            int m = m0 + wm * 32 + mi * 16 + (lane >> 2) + u * 8;
            float inv = gamma[m] / sqrtf(var[m] + 1e-5f);
            float off = beta[m] - mean[m] * inv;
#pragma unroll
            for (int ni = 0; ni < 4; ++ni) {
                vv[mi][u][ni][0] = acc[mi][ni][u * 2 + 0] * inv + off;
                vv[mi][u][ni][1] = acc[mi][ni][u * 2 + 1] * inv + off;
            }
        }

    if (MODE) {
        const int nb = n0 + wl * 32 + (lane & 3) * 2;
#pragma unroll
        for (int mi = 0; mi < 2; ++mi)
#pragma unroll
            for (int u = 0; u < 2; ++u) {
                int m = m0 + wm * 32 + mi * 16 + (lane >> 2) + u * 8;
#pragma unroll
                for (int ni = 0; ni < 4; ++ni) {
                    int n = nb + ni * 8;
                    const float2 rx = *(const float2*)(resid + (size_t)t2b * (C_ * L_) +
                                                       (size_t)m * L_ + n);
                    *(float2*)(outp + (size_t)t2b * (C_ * L_) + (size_t)m * L_ + n) =
                        make_float2(vv[mi][u][ni][0] + rx.x, vv[mi][u][ni][1] + rx.y);
                }
            }
    } else {
        // All 3 splits staged at once (55KB fits the stage buffers), ONE barrier.
        u16* stg = (u16*)dyn;
        __syncthreads();                          // stage buffers now reusable
#pragma unroll
        for (int s = 0; s < 3; ++s) {
#pragma unroll
            for (int mi = 0; mi < 2; ++mi)
#pragma unroll
                for (int u = 0; u < 2; ++u) {
                    int ml = wm * 32 + mi * 16 + (lane >> 2) + u * 8;
#pragma unroll
                    for (int ni = 0; ni < 4; ++ni) {
                        int nl = wl * 32 + ni * 8 + (lane & 3) * 2;
                        __nv_bfloat16 h0 = __float2bfloat16(vv[mi][u][ni][0]);
                        vv[mi][u][ni][0] -= __bfloat162float(h0);
                        __nv_bfloat16 h1 = __float2bfloat16(vv[mi][u][ni][1]);
                        vv[mi][u][ni][1] -= __bfloat162float(h1);
                        *(ushort2*)&stg[s * 9216 + ml * 72 + nl] =
                            make_ushort2(bf_bits(h0), bf_bits(h1));
                    }
                }
        }
        __syncthreads();
#pragma unroll
        for (int s = 0; s < 3; ++s)
#pragma unroll
            for (int q = 0; q < 4; ++q) {
                int idx = tid + q * 256, r = idx >> 3, c = idx & 7;
                uint4 w = *(uint4*)&stg[s * 9216 + r * 72 + c * 8];
                int m = m0 + r, hh = m / 96, rr = m % 96;
                u16* dst;
                if (rr < 48)
                    dst = (u16*)g_y1s + ((size_t)(t2b * 8 + hh) * 3 + s) * 49152 +
                          (size_t)rr * 1024 + n0 + c * 8;
                else
                    dst = (u16*)g_y2s + ((size_t)(t2b * 8 + hh) * 3 + s) * 65536 +
                          (size_t)(rr - 48) * 1024 + n0 + c * 8;
                *(uint4*)dst = w;
            }
    }
}

// ---------------------------------------------------------------------------
// K3: HMMA attn  attnT[m][l] = sum_{s,d} xr[d][m] * y1s[s][d][l], fused t-scan
//   256 threads, 8 warps (4m x 2l), CTA 128m x 64l, 2 CTA/SM (R14 geometry).
//   Spike output u8; early deferred double-buffered flush.
// ---------------------------------------------------------------------------
#define AP_A 136
#define AP_B 72
#define AT_AE (48 * AP_A)                   // 6528
#define AT_STG (AT_AE + 144 * AP_B)         // 16896
__global__ __launch_bounds__(256, 2) void k_attn_mma() {
    extern __shared__ __nv_bfloat16 dyn[];
    const int bh = blockIdx.z, b = bh >> 3, h = bh & 7;
    const int m0 = blockIdx.y * 128, l0 = blockIdx.x * 64;
    const int tid = threadIdx.x, lane = tid & 31, wid = tid >> 5;
    const int wm = wid & 3, wl = wid >> 2;
    const unsigned sDyn = smem_u32(dyn);

    float mem[2][4][4];
#pragma unroll
    for (int i = 0; i < 2; ++i)
#pragma unroll
        for (int j = 0; j < 4; ++j)
#pragma unroll
            for (int q = 0; q < 4; ++q) mem[i][j][q] = 0.f;

    const int at_r = (lane & 7) + ((lane >> 4) & 1) * 8;
    const int at_c = wm * 32 + ((lane >> 3) & 1) * 8;
    const int bt_r = (lane & 7) + ((lane >> 3) & 1) * 8;
    const int bt_c = wl * 32 + ((lane >> 4) & 1) * 8;

    auto load_stage = [&](int t, int buf) {
        const int t2b = t * 2 + b;
        const __nv_bfloat16* xr = g_xsb + ((size_t)t2b * C_ + h * D_) * L_ + m0;
        const __nv_bfloat16* y1 = g_y1s + (size_t)(t2b * 8 + h) * 3 * 49152 + l0;
        unsigned base = sDyn + buf * (AT_STG * 2);
#pragma unroll
        for (int q = 0; q < 3; ++q) {                       // A: 768 cp16
            int id = tid + q * 256;
            int r = id >> 4, c = id & 15;
            cp16(base + 2u * (r * AP_A + c * 8), xr + (size_t)r * L_ + c * 8);
        }
#pragma unroll
        for (int q = 0; q < 5; ++q) {                       // B: 1152 cp16
            int id = tid + q * 256;
            if (id < 1152) {
                int sr = id >> 3, c = id & 7;
                cp16(base + 2u * (AT_AE + sr * AP_B + c * 8), y1 + (size_t)sr * 1024 + c * 8);
            }
        }
        cp_commit();
    };

    u8* stg0 = (u8*)(dyn + 2 * AT_STG);      // two 128x80 u8 staging tiles
    u8* stgs[2] = {stg0, stg0 + 128 * 80};

    auto flush = [&](int t) {
        const u8* src = stgs[t & 1];
        u8* og = g_spkU + (size_t)(t * BH_ + bh) * LL;
#pragma unroll
        for (int q = 0; q < 2; ++q) {
            int idx = tid + q * 256, r = idx >> 2, c = idx & 3;
            uint4 w = *(const uint4*)&src[r * 80 + c * 16];
            *(uint4*)(og + (size_t)(m0 + r) * L_ + l0 + c * 16) = w;
        }
    };

    load_stage(0, 0);
#pragma unroll
    for (int t = 0; t < T_; ++t) {
        cp_wait0();
        __syncthreads();                       // visibility + WAR + stg ordering
        if (t < 3) load_stage(t + 1, (t + 1) & 1);
        if (t > 0) flush(t - 1);               // early: fills LDSM-dependency bubbles
        const unsigned sA = sDyn + (t & 1) * (AT_STG * 2);
        const unsigned sB = sA + AT_AE * 2;

        unsigned a[3][2][4];
#pragma unroll
        for (int kk = 0; kk < 3; ++kk)
#pragma unroll
            for (int mi = 0; mi < 2; ++mi)
                ldsm_x4t(a[kk][mi], sA + 2u * ((kk * 16 + at_r) * AP_A + at_c + mi * 16));

        float acc[2][4][4] = {};
#pragma unroll
        for (int s = 0; s < 3; ++s)
#pragma unroll
            for (int kk = 0; kk < 3; ++kk) {
                unsigned bfr[4][2];
#pragma unroll
                for (int pair = 0; pair < 2; ++pair) {
                    unsigned bb[4];
                    ldsm_x4t(bb, sB + 2u * ((s * 48 + kk * 16 + bt_r) * AP_B + bt_c + pair * 16));
                    bfr[pair * 2][0] = bb[0]; bfr[pair * 2][1] = bb[1];
                    bfr[pair * 2 + 1][0] = bb[2]; bfr[pair * 2 + 1][1] = bb[3];
                }
#pragma unroll
                for (int mi = 0; mi < 2; ++mi)
#pragma unroll
                    for (int ni = 0; ni < 4; ++ni)
                        mma16816(acc[mi][ni], a[kk][mi], bfr[ni]);
            }

        // membrane update + u8 spike staging
        u8* stg = stgs[t & 1];
#pragma unroll
        for (int mi = 0; mi < 2; ++mi)
#pragma unroll
            for (int u = 0; u < 2; ++u) {
                int ml = wm * 32 + mi * 16 + (lane >> 2) + u * 8;
#pragma unroll
                for (int ni = 0; ni < 4; ++ni) {
                    float* mp = &mem[mi][ni][u * 2];
                    mp[0] = mp[0] * 0.25f * ((mp[0] > 0.5f) ? 0.f : 1.f) + acc[mi][ni][u * 2];
                    mp[1] = mp[1] * 0.25f * ((mp[1] > 0.5f) ? 0.f : 1.f) + acc[mi][ni][u * 2 + 1];
                    int nl = wl * 32 + ni * 8 + (lane & 3) * 2;
                    *(uchar2*)&stg[ml * 80 + nl] =
                        make_uchar2(mp[0] > 0.5f ? 1 : 0, mp[1] > 0.5f ? 1 : 0);
                }
            }
    }
    __syncthreads();
    flush(3);
}

// ---------------------------------------------------------------------------
// K4: HMMA GEMM (transposed)  D[d][m] = sum_{s,l} y2s[s][d][l] * spk[m][l]
//   A = y2s (bf16, ldsm non-trans). B = spikes u8, expanded to 2-reg B-frags
//   via LDS.U16+PRMT (reused across all 3 splits). N-tile 256 -> grid 256 CTAs
//   (single resident wave). Output lands in g_o1's native [d][m] layout.
//   smem: A[2][144*72*2] | Bu8[2][256*80]
// ---------------------------------------------------------------------------
#define G2_AB   (144 * 72 * 2)              // 20736 B per A stage
#define G2_U8   (256 * 80)                  // 20480 B per B-u8 stage
#define OFF_U8  (2 * G2_AB)                 // 41472
#define G2_SMEM (OFF_U8 + 2 * G2_U8)        // 82432
__global__ __launch_bounds__(256, 2) void k_gemm2_mma() {
    extern __shared__ char dynG[];
    const int z  = blockIdx.y;
    const int m0 = blockIdx.x * 256;
    const int t = z >> 4, bh = z & 15, b = bh >> 3, h = bh & 7;
    const int t2b = t * 2 + b;

    const int tid = threadIdx.x, lane = tid & 31, wid = tid >> 5;
    const unsigned sDyn = smem_u32(dynG);

    const __nv_bfloat16* Agl = g_y2s + (size_t)(t2b * 8 + h) * 3 * 65536;
    const u8*            Bgl = g_spkU + (size_t)z * LL + (size_t)m0 * L_;

    float acc[3][4][4] = {};
    const int a_r = lane & 15;                 // + s*48 + mt*16
    const int a_c = (lane >> 4) * 8;           // + kk*16
    const int bn_row = lane >> 2;              // n within 8-row group
    const int bn_off = (lane & 3) * 2;         // k pair offset

    auto load_stage = [&](int it, int buf) {
        const int kt = it * 64;
        // A (y2s): 3 x 48 rows x 128B = 1152 cp16
#pragma unroll
        for (int q = 0; q < 5; ++q) {
            int id = tid + q * 256;
            if (id < 1152) {
                int s = id / 384, rr = (id % 384) >> 3, c = id & 7;
                cp16(sDyn + buf * G2_AB + 2u * ((s * 48 + rr) * 72 + c * 8),
                     Agl + (size_t)s * 65536 + (size_t)rr * 1024 + kt + c * 8);
            }
        }
        // B u8 (spikes): 256 rows x 64B = 1024 cp16
#pragma unroll
        for (int q = 0; q < 4; ++q) {
            int id = tid + q * 256, r = id >> 2, c = id & 3;
            cp16(sDyn + OFF_U8 + buf * G2_U8 + r * 80 + c * 16,
                 Bgl + (size_t)r * L_ + kt + c * 16);
        }
        cp_commit();
    };

    load_stage(0, 0);
    for (int it = 0; it < 16; ++it) {
        cp_wait0();
        __syncthreads();                          // visibility + WAR guard
        if (it < 15) load_stage(it + 1, (it + 1) & 1);

        const unsigned sA = sDyn + (it & 1) * G2_AB;
        const u8* Bu = (const u8*)(dynG + OFF_U8 + (it & 1) * G2_U8);

        // B fragments (spikes): expand once per chunk, reused across 3 splits
        unsigned bf[4][4][2];
#pragma unroll
        for (int nt = 0; nt < 4; ++nt)
#pragma unroll
            for (int kk = 0; kk < 4; ++kk) {
                const u8* p = Bu + (wid * 32 + nt * 8 + bn_row) * 80 + kk * 16 + bn_off;
                bf[nt][kk][0] = spk_frag(p);
                bf[nt][kk][1] = spk_frag(p + 8);
            }
#pragma unroll
        for (int s = 0; s < 3; ++s)
#pragma unroll
            for (int kk = 0; kk < 4; ++kk) {
                unsigned a[3][4];
#pragma unroll
                for (int mt = 0; mt < 3; ++mt)
                    ldsm_x4(a[mt], sA + 2u * ((s * 48 + mt * 16 + a_r) * 72 + kk * 16 + a_c));
#pragma unroll
                for (int mt = 0; mt < 3; ++mt)
#pragma unroll
                    for (int nt = 0; nt < 4; ++nt)
                        mma16816(acc[mt][nt], a[mt], bf[nt][kk]);
            }
    }

    // Epilogue: D[d][m] fragments -> g_o1 native layout (row-contiguous)
    float* O = g_o1 + (size_t)t2b * (C_ * L_) + (size_t)(h * D_) * L_;
#pragma unroll
    for (int mt = 0; mt < 3; ++mt) {
        int d = mt * 16 + (lane >> 2);
#pragma unroll
        for (int nt = 0; nt < 4; ++nt) {
            int m = m0 + wid * 32 + nt * 8 + (lane & 3) * 2;
            *(float2*)(O + (size_t)d * L_ + m)       = make_float2(acc[mt][nt][0], acc[mt][nt][1]);
            *(float2*)(O + (size_t)(d + 8) * L_ + m) = make_float2(acc[mt][nt][2], acc[mt][nt][3]);
        }
    }
}

// ---------------------------------------------------------------------------
// K5: membrane scan over out1 -> bf16 spikes
// ---------------------------------------------------------------------------
__global__ __launch_bounds__(256) void k_scan_o1() {
    int i = blockIdx.x * 256 + threadIdx.x;
    if (i >= BCL) return;
    float mem = 0.f, sp = 0.f;
#pragma unroll
    for (int t = 0; t < T_; ++t) {
        mem = mem * 0.25f * (1.f - sp) + g_o1[(size_t)t * BCL + i];
        sp  = (mem > 0.5f) ? 1.f : 0.f;
        ((u16*)g_o1b)[(size_t)t * BCL + i] = (mem > 0.5f) ? 0x3F80 : 0;
    }
}

// ---------------------------------------------------------------------------
extern "C" void kernel_launch(void* const* d_in, const int* in_sizes, int n_in,
                              void* d_out, int out_size) {
    (void)in_sizes; (void)n_in; (void)out_size;
    const float* x   = (const float*)d_in[0];
    const float* W_w = (const float*)d_in[1];
    const float* g1  = (const float*)d_in[2];
    const float* be1 = (const float*)d_in[3];
    const float* me1 = (const float*)d_in[4];
    const float* v1  = (const float*)d_in[5];
    const float* pw  = (const float*)d_in[6];
    const float* g2  = (const float*)d_in[7];
    const float* be2 = (const float*)d_in[8];
    const float* me2 = (const float*)d_in[9];
    const float* v2  = (const float*)d_in[10];
    float* out = (float*)d_out;

    const int smW0 = 3 * (3 * 128 * WP_A + 32 * WP_B) * 2;   // 105984
    const int smW1 = 3 * (2 * 128 * WP_A + 32 * WP_B) * 2;   // 75264
    const int smA  = 2 * AT_STG * 2 + 2 * 128 * 80;          // 88064
    const int smG  = G2_SMEM;                                // 82432
    cudaFuncSetAttribute(k_wgemm<3, 0>, cudaFuncAttributeMaxDynamicSharedMemorySize, smW0);
    cudaFuncSetAttribute(k_wgemm<2, 1>, cudaFuncAttributeMaxDynamicSharedMemorySize, smW1);
    cudaFuncSetAttribute(k_attn_mma,    cudaFuncAttributeMaxDynamicSharedMemorySize, smA);
    cudaFuncSetAttribute(k_gemm2_mma,   cudaFuncAttributeMaxDynamicSharedMemorySize, smG);

    k_prep<<<BCL / 256 + (C2_ * C_ + C_ * C_) / 256, 256>>>(x, W_w, pw);
    k_wgemm<3, 0><<<dim3(L_ / 64, C2_ / 128, T_ * B_), 256, smW0>>>(
        g1, be1, me1, v1, nullptr, nullptr, C2_);
    k_attn_mma<<<dim3(L_ / 64, L_ / 128, BH_), 256, smA>>>();
    k_gemm2_mma<<<dim3(L_ / 256, T_ * BH_), 256, smG>>>();
    k_scan_o1<<<BCL / 256, 256>>>();
    k_wgemm<2, 1><<<dim3(L_ / 64, C_ / 128, T_ * B_), 256, smW1>>>(
        g2, be2, me2, v2, x, out, C_);
}